// round 1
// baseline (speedup 1.0000x reference)
#include <cuda_runtime.h>

#define N_NODES 8192
#define E_EDGES 262144
#define IN_DIM  512
#define HID_DIM 256
#define Z_DIM   64

// Scratch (device globals: allocation-free)
__device__ float g_h0[N_NODES * HID_DIM];   // x @ W1
__device__ float g_h [N_NODES * HID_DIM];   // relu(spmm(h0))
__device__ float g_p [N_NODES * Z_DIM];     // h @ W2
__device__ int   g_rowptr[N_NODES + 1];

// ---------------------------------------------------------------------------
// CSR row pointer from sorted edge_row: rowptr[i] = lower_bound(edge_row, i)
// ---------------------------------------------------------------------------
__global__ void rowptr_kernel(const int* __restrict__ er) {
    int i = blockIdx.x * blockDim.x + threadIdx.x;
    if (i > N_NODES) return;
    int lo = 0, hi = E_EDGES;
    while (lo < hi) {
        int mid = (lo + hi) >> 1;
        if (er[mid] < i) lo = mid + 1; else hi = mid;
    }
    g_rowptr[i] = lo;
}

// ---------------------------------------------------------------------------
// Tiled fp32 GEMM: C[M,N] = A[M,K] @ B[K,N].  BM=BN=64, BK=16, 4x4 microtile.
// All problem dims divide the tile sizes exactly (8192/512/256/64).
// ---------------------------------------------------------------------------
template<int BM, int BN, int BK, int TM, int TN>
__global__ __launch_bounds__(256) void sgemm_nn(
    const float* __restrict__ A, const float* __restrict__ B,
    float* __restrict__ C, int M, int K, int N)
{
    __shared__ float As[BK][BM + 4];   // +4 keeps float4 alignment per row
    __shared__ float Bs[BK][BN];
    const int NT = (BM / TM) * (BN / TN);       // 256
    const int tid = threadIdx.x;
    const int tx = tid % (BN / TN);
    const int ty = tid / (BN / TN);
    const int mbase = blockIdx.y * BM;
    const int nbase = blockIdx.x * BN;

    float acc[TM][TN] = {};

    for (int kk = 0; kk < K; kk += BK) {
        #pragma unroll
        for (int idx = tid; idx < BM * BK; idx += NT) {
            int m = idx / BK, k = idx % BK;
            As[k][m] = A[(size_t)(mbase + m) * K + kk + k];
        }
        #pragma unroll
        for (int idx = tid; idx < BK * BN; idx += NT) {
            int k = idx / BN, n = idx % BN;
            Bs[k][n] = B[(size_t)(kk + k) * N + nbase + n];
        }
        __syncthreads();

        #pragma unroll
        for (int k = 0; k < BK; ++k) {
            float4 a4 = *(const float4*)&As[k][ty * TM];
            float4 b4 = *(const float4*)&Bs[k][tx * TN];
            float a[4] = {a4.x, a4.y, a4.z, a4.w};
            float b[4] = {b4.x, b4.y, b4.z, b4.w};
            #pragma unroll
            for (int i = 0; i < TM; ++i)
                #pragma unroll
                for (int j = 0; j < TN; ++j)
                    acc[i][j] += a[i] * b[j];
        }
        __syncthreads();
    }

    #pragma unroll
    for (int i = 0; i < TM; ++i) {
        size_t off = (size_t)(mbase + ty * TM + i) * N + nbase + tx * TN;
        *(float4*)&C[off] = make_float4(acc[i][0], acc[i][1], acc[i][2], acc[i][3]);
    }
}

// ---------------------------------------------------------------------------
// SpMM: out[r,d] = sum_{e in row r} w[e] * hin[col[e], d]   (+ optional relu)
// One row per blockDim.y lane; thread d owns one feature column.
// ---------------------------------------------------------------------------
template<int D, bool RELU>
__global__ void spmm_kernel(const float* __restrict__ hin,
                            const int*   __restrict__ col,
                            const float* __restrict__ wgt,
                            float* __restrict__ hout)
{
    int row = blockIdx.x * blockDim.y + threadIdx.y;
    int d = threadIdx.x;
    int s = g_rowptr[row];
    int e = g_rowptr[row + 1];
    float acc = 0.f;
    int i = s;
    for (; i + 4 <= e; i += 4) {
        int   c0 = col[i+0], c1 = col[i+1], c2 = col[i+2], c3 = col[i+3];
        float w0 = wgt[i+0], w1 = wgt[i+1], w2 = wgt[i+2], w3 = wgt[i+3];
        acc += w0 * hin[(size_t)c0 * D + d];
        acc += w1 * hin[(size_t)c1 * D + d];
        acc += w2 * hin[(size_t)c2 * D + d];
        acc += w3 * hin[(size_t)c3 * D + d];
    }
    for (; i < e; ++i)
        acc += wgt[i] * hin[(size_t)col[i] * D + d];
    if (RELU) acc = fmaxf(acc, 0.f);
    hout[(size_t)row * D + d] = acc;
}

// ---------------------------------------------------------------------------
// recon = Z @ Z^T.  128x128 output tile per block, K=64 fully staged in smem
// (transposed + padded so compute loads are conflict-free float4).
// ---------------------------------------------------------------------------
#define ZT  128
#define ZLD 132   // 132*4 = 528 bytes: 16B-aligned rows, conflict-spreading pad

__global__ __launch_bounds__(256) void zzt_kernel(
    const float* __restrict__ Z, float* __restrict__ C)
{
    extern __shared__ float sm[];
    float* Zas = sm;                   // [Z_DIM][ZLD]: Zas[k][r] = Z[rbase+r][k]
    float* Zbs = sm + Z_DIM * ZLD;     // [Z_DIM][ZLD]: Zbs[k][c] = Z[cbase+c][k]

    const int tid = threadIdx.x;
    const int tx = tid & 15;
    const int ty = tid >> 4;
    const int rbase = blockIdx.y * ZT;
    const int cbase = blockIdx.x * ZT;

    const int k4 = (tid & 15) * 4;
    for (int rr = tid >> 4; rr < ZT; rr += 16) {
        float4 va = *(const float4*)&Z[(size_t)(rbase + rr) * Z_DIM + k4];
        Zas[(k4+0)*ZLD + rr] = va.x;
        Zas[(k4+1)*ZLD + rr] = va.y;
        Zas[(k4+2)*ZLD + rr] = va.z;
        Zas[(k4+3)*ZLD + rr] = va.w;
        float4 vb = *(const float4*)&Z[(size_t)(cbase + rr) * Z_DIM + k4];
        Zbs[(k4+0)*ZLD + rr] = vb.x;
        Zbs[(k4+1)*ZLD + rr] = vb.y;
        Zbs[(k4+2)*ZLD + rr] = vb.z;
        Zbs[(k4+3)*ZLD + rr] = vb.w;
    }
    __syncthreads();

    float acc[8][8] = {};
    const int ra = ty * 8;
    const int cb = tx * 8;

    #pragma unroll 4
    for (int k = 0; k < Z_DIM; ++k) {
        float4 a0 = *(const float4*)&Zas[k * ZLD + ra];
        float4 a1 = *(const float4*)&Zas[k * ZLD + ra + 4];
        float4 b0 = *(const float4*)&Zbs[k * ZLD + cb];
        float4 b1 = *(const float4*)&Zbs[k * ZLD + cb + 4];
        float a[8] = {a0.x, a0.y, a0.z, a0.w, a1.x, a1.y, a1.z, a1.w};
        float b[8] = {b0.x, b0.y, b0.z, b0.w, b1.x, b1.y, b1.z, b1.w};
        #pragma unroll
        for (int i = 0; i < 8; ++i)
            #pragma unroll
            for (int j = 0; j < 8; ++j)
                acc[i][j] += a[i] * b[j];
    }

    #pragma unroll
    for (int i = 0; i < 8; ++i) {
        size_t off = (size_t)(rbase + ra + i) * N_NODES + cbase + cb;
        *(float4*)&C[off]     = make_float4(acc[i][0], acc[i][1], acc[i][2], acc[i][3]);
        *(float4*)&C[off + 4] = make_float4(acc[i][4], acc[i][5], acc[i][6], acc[i][7]);
    }
}

// ---------------------------------------------------------------------------
extern "C" void kernel_launch(void* const* d_in, const int* in_sizes, int n_in,
                              void* d_out, int out_size)
{
    const float* x    = (const float*)d_in[0];
    const float* w1   = (const float*)d_in[1];
    const float* w2   = (const float*)d_in[2];
    const int*   erow = (const int*)  d_in[3];
    const int*   ecol = (const int*)  d_in[4];
    const float* ew   = (const float*)d_in[5];

    float* out   = (float*)d_out;
    float* recon = out;                                   // [N, N]
    float* z     = out + (size_t)N_NODES * N_NODES;       // [N, Z_DIM]

    float *h0, *h, *p;
    cudaGetSymbolAddress((void**)&h0, g_h0);
    cudaGetSymbolAddress((void**)&h,  g_h);
    cudaGetSymbolAddress((void**)&p,  g_p);

    // 1. CSR row pointers
    rowptr_kernel<<<(N_NODES + 256) / 256, 256>>>(erow);

    // 2. h0 = x @ W1   [8192 x 256]
    dim3 g1(HID_DIM / 64, N_NODES / 64);
    sgemm_nn<64, 64, 16, 4, 4><<<g1, 256>>>(x, w1, h0, N_NODES, IN_DIM, HID_DIM);

    // 3. h = relu(spmm(h0))
    spmm_kernel<HID_DIM, true><<<N_NODES, dim3(HID_DIM, 1)>>>(h0, ecol, ew, h);

    // 4. p = h @ W2    [8192 x 64]
    dim3 g2(Z_DIM / 64, N_NODES / 64);
    sgemm_nn<64, 64, 16, 4, 4><<<g2, 256>>>(h, w2, p, N_NODES, HID_DIM, Z_DIM);

    // 5. z = spmm(p)  -> written directly into output tail
    spmm_kernel<Z_DIM, false><<<N_NODES / 4, dim3(Z_DIM, 4)>>>(p, ecol, ew, z);

    // 6. recon = z @ z^T
    const int zzt_smem = 2 * Z_DIM * ZLD * (int)sizeof(float);   // 67584 B
    cudaFuncSetAttribute(zzt_kernel, cudaFuncAttributeMaxDynamicSharedMemorySize, zzt_smem);
    zzt_kernel<<<dim3(N_NODES / ZT, N_NODES / ZT), 256, zzt_smem>>>(z, recon);
}

// round 2
// speedup vs baseline: 1.0880x; 1.0880x over previous
#include <cuda_runtime.h>

#define N_NODES 8192
#define E_EDGES 262144
#define IN_DIM  512
#define HID_DIM 256
#define Z_DIM   64

typedef unsigned long long ull;

// Scratch (device globals: allocation-free)
__device__ float g_h0[N_NODES * HID_DIM];   // x @ W1
__device__ float g_h [N_NODES * HID_DIM];   // relu(spmm(h0))
__device__ float g_p [N_NODES * Z_DIM];     // h @ W2
__device__ int   g_rowptr[N_NODES + 1];

// ---------------------------------------------------------------------------
// Packed f32x2 helpers (Blackwell: fma.rn.f32x2 doubles fp32 FMA throughput;
// ptxas never emits it from C++ — PTX only).
// ---------------------------------------------------------------------------
__device__ __forceinline__ ull pack2(float x, float y) {
    ull r; asm("mov.b64 %0, {%1, %2};" : "=l"(r) : "f"(x), "f"(y)); return r;
}
__device__ __forceinline__ ull dup2(float x) { return pack2(x, x); }
__device__ __forceinline__ ull fma2(ull a, ull b, ull c) {
    ull d; asm("fma.rn.f32x2 %0, %1, %2, %3;" : "=l"(d) : "l"(a), "l"(b), "l"(c));
    return d;
}
__device__ __forceinline__ float2 unpack2(ull v) {
    float2 f; asm("mov.b64 {%0, %1}, %2;" : "=f"(f.x), "=f"(f.y) : "l"(v)); return f;
}

// ---------------------------------------------------------------------------
// CSR row pointer from sorted edge_row: rowptr[i] = lower_bound(edge_row, i)
// ---------------------------------------------------------------------------
__global__ void rowptr_kernel(const int* __restrict__ er) {
    int i = blockIdx.x * blockDim.x + threadIdx.x;
    if (i > N_NODES) return;
    int lo = 0, hi = E_EDGES;
    while (lo < hi) {
        int mid = (lo + hi) >> 1;
        if (er[mid] < i) lo = mid + 1; else hi = mid;
    }
    g_rowptr[i] = lo;
}

// ---------------------------------------------------------------------------
// Tiled fp32 GEMM with f32x2 inner product: C[M,N] = A[M,K] @ B[K,N].
// TM=4, TN=4 fixed (4x2 f32x2 accumulators per thread).
// ---------------------------------------------------------------------------
template<int BM, int BN, int BK>
__global__ void sgemm_nn(
    const float* __restrict__ A, const float* __restrict__ B,
    float* __restrict__ C, int M, int K, int N)
{
    __shared__ float As[BK][BM + 4];
    __shared__ float Bs[BK][BN];
    const int NT = (BM / 4) * (BN / 4);
    const int tid = threadIdx.x;
    const int tx = tid % (BN / 4);
    const int ty = tid / (BN / 4);
    const int mbase = blockIdx.y * BM;
    const int nbase = blockIdx.x * BN;

    ull acc[4][2] = {};

    for (int kk = 0; kk < K; kk += BK) {
        #pragma unroll
        for (int idx = tid; idx < BM * BK; idx += NT) {
            int m = idx / BK, k = idx % BK;
            As[k][m] = A[(size_t)(mbase + m) * K + kk + k];
        }
        #pragma unroll
        for (int idx = tid; idx < BK * BN; idx += NT) {
            int k = idx / BN, n = idx % BN;
            Bs[k][n] = B[(size_t)(kk + k) * N + nbase + n];
        }
        __syncthreads();

        #pragma unroll
        for (int k = 0; k < BK; ++k) {
            float4 a4 = *(const float4*)&As[k][ty * 4];
            float4 b4 = *(const float4*)&Bs[k][tx * 4];
            ull b2[2] = { pack2(b4.x, b4.y), pack2(b4.z, b4.w) };
            float a[4] = { a4.x, a4.y, a4.z, a4.w };
            #pragma unroll
            for (int i = 0; i < 4; ++i) {
                ull ad = dup2(a[i]);
                acc[i][0] = fma2(ad, b2[0], acc[i][0]);
                acc[i][1] = fma2(ad, b2[1], acc[i][1]);
            }
        }
        __syncthreads();
    }

    #pragma unroll
    for (int i = 0; i < 4; ++i) {
        float2 c0 = unpack2(acc[i][0]);
        float2 c1 = unpack2(acc[i][1]);
        size_t off = (size_t)(mbase + ty * 4 + i) * N + nbase + tx * 4;
        *(float4*)&C[off] = make_float4(c0.x, c0.y, c1.x, c1.y);
    }
}

// ---------------------------------------------------------------------------
// SpMM: out[r,2d..2d+1] = sum_{e in row r} w[e] * hin[col[e], 2d..2d+1]
// float2 lanes, f32x2 FMA. blockDim.x = D/2, blockDim.y rows per block.
// ---------------------------------------------------------------------------
template<int D, bool RELU>
__global__ void spmm_kernel(const float* __restrict__ hin,
                            const int*   __restrict__ col,
                            const float* __restrict__ wgt,
                            float* __restrict__ hout)
{
    int row = blockIdx.x * blockDim.y + threadIdx.y;
    int d2 = threadIdx.x * 2;
    int s = g_rowptr[row];
    int e = g_rowptr[row + 1];
    ull acc = 0;
    int i = s;
    for (; i + 4 <= e; i += 4) {
        int   c0 = col[i+0], c1 = col[i+1], c2 = col[i+2], c3 = col[i+3];
        float w0 = wgt[i+0], w1 = wgt[i+1], w2 = wgt[i+2], w3 = wgt[i+3];
        float2 v0 = *(const float2*)&hin[(size_t)c0 * D + d2];
        float2 v1 = *(const float2*)&hin[(size_t)c1 * D + d2];
        float2 v2 = *(const float2*)&hin[(size_t)c2 * D + d2];
        float2 v3 = *(const float2*)&hin[(size_t)c3 * D + d2];
        acc = fma2(dup2(w0), pack2(v0.x, v0.y), acc);
        acc = fma2(dup2(w1), pack2(v1.x, v1.y), acc);
        acc = fma2(dup2(w2), pack2(v2.x, v2.y), acc);
        acc = fma2(dup2(w3), pack2(v3.x, v3.y), acc);
    }
    for (; i < e; ++i) {
        float2 v = *(const float2*)&hin[(size_t)col[i] * D + d2];
        acc = fma2(dup2(wgt[i]), pack2(v.x, v.y), acc);
    }
    float2 r = unpack2(acc);
    if (RELU) { r.x = fmaxf(r.x, 0.f); r.y = fmaxf(r.y, 0.f); }
    *(float2*)&hout[(size_t)row * D + d2] = r;
}

// ---------------------------------------------------------------------------
// recon = Z @ Z^T, symmetric: one block per lower-triangle 128x128 tile.
// K=64 fully staged (transposed) in smem. f32x2 8x8 microtile.
// Off-diagonal blocks mirror their tile via a swizzled smem transpose bounce.
// ---------------------------------------------------------------------------
#define ZT  128
#define ZLD 132

__global__ __launch_bounds__(256) void zzt_sym_kernel(
    const float* __restrict__ Z, float* __restrict__ C)
{
    extern __shared__ float sm[];
    float* Zas = sm;                   // [Z_DIM][ZLD]: Zas[k][r] = Z[rbase+r][k]
    float* Zbs = sm + Z_DIM * ZLD;     // [Z_DIM][ZLD]: Zbs[k][c] = Z[cbase+c][k]

    // triangular index -> (bx, by), bx <= by
    const int l = blockIdx.x;
    int by = (int)((sqrtf(8.0f * (float)l + 1.0f) - 1.0f) * 0.5f);
    while ((by + 1) * (by + 2) / 2 <= l) ++by;
    while (by * (by + 1) / 2 > l) --by;
    const int bx = l - by * (by + 1) / 2;

    const int tid = threadIdx.x;
    const int tx = tid & 15;
    const int ty = tid >> 4;
    const int rbase = by * ZT;
    const int cbase = bx * ZT;

    const int k4 = tx * 4;
    for (int rr = ty; rr < ZT; rr += 16) {
        float4 va = *(const float4*)&Z[(size_t)(rbase + rr) * Z_DIM + k4];
        Zas[(k4+0)*ZLD + rr] = va.x;
        Zas[(k4+1)*ZLD + rr] = va.y;
        Zas[(k4+2)*ZLD + rr] = va.z;
        Zas[(k4+3)*ZLD + rr] = va.w;
        float4 vb = *(const float4*)&Z[(size_t)(cbase + rr) * Z_DIM + k4];
        Zbs[(k4+0)*ZLD + rr] = vb.x;
        Zbs[(k4+1)*ZLD + rr] = vb.y;
        Zbs[(k4+2)*ZLD + rr] = vb.z;
        Zbs[(k4+3)*ZLD + rr] = vb.w;
    }
    __syncthreads();

    ull acc[8][4] = {};
    const int ra = ty * 8;
    const int cb = tx * 8;

    #pragma unroll 4
    for (int k = 0; k < Z_DIM; ++k) {
        float4 a0 = *(const float4*)&Zas[k * ZLD + ra];
        float4 a1 = *(const float4*)&Zas[k * ZLD + ra + 4];
        float4 b0 = *(const float4*)&Zbs[k * ZLD + cb];
        float4 b1 = *(const float4*)&Zbs[k * ZLD + cb + 4];
        ull b2[4] = { pack2(b0.x, b0.y), pack2(b0.z, b0.w),
                      pack2(b1.x, b1.y), pack2(b1.z, b1.w) };
        float a[8] = { a0.x, a0.y, a0.z, a0.w, a1.x, a1.y, a1.z, a1.w };
        #pragma unroll
        for (int i = 0; i < 8; ++i) {
            ull ad = dup2(a[i]);
            #pragma unroll
            for (int jp = 0; jp < 4; ++jp)
                acc[i][jp] = fma2(ad, b2[jp], acc[i][jp]);
        }
    }

    // unpack accumulators
    float av[8][8];
    #pragma unroll
    for (int i = 0; i < 8; ++i)
        #pragma unroll
        for (int jp = 0; jp < 4; ++jp) {
            float2 v = unpack2(acc[i][jp]);
            av[i][2*jp]   = v.x;
            av[i][2*jp+1] = v.y;
        }

    // write lower-triangle tile (coalesced float4)
    #pragma unroll
    for (int i = 0; i < 8; ++i) {
        size_t off = (size_t)(rbase + ra + i) * N_NODES + cbase + cb;
        *(float4*)&C[off]     = make_float4(av[i][0], av[i][1], av[i][2], av[i][3]);
        *(float4*)&C[off + 4] = make_float4(av[i][4], av[i][5], av[i][6], av[i][7]);
    }

    if (bx == by) return;

    // mirror tile via smem transpose bounce.
    // T[a][b] = value for output (cbase+a, rbase+b); stored with 8-granule
    // rotation swizzle: col' = (b + (a & 120)) & 127 (4-way conflicts max,
    // float4-contiguous on the read side).
    __syncthreads();
    float* T = sm;   // reuse: 128 * 132 floats = exactly the staged-Z footprint
    #pragma unroll
    for (int j = 0; j < 8; ++j) {
        int a = cb + j;
        int rot = a & 120;
        #pragma unroll
        for (int i = 0; i < 8; ++i) {
            int b = ra + i;
            T[a * ZLD + ((b + rot) & 127)] = av[i][j];
        }
    }
    __syncthreads();

    #pragma unroll
    for (int i = 0; i < 8; ++i) {
        int a = ty * 8 + i;            // local row of the mirror tile
        int rot = a & 120;
        float4 v0 = *(const float4*)&T[a * ZLD + ((tx * 8     + rot) & 127)];
        float4 v1 = *(const float4*)&T[a * ZLD + ((tx * 8 + 4 + rot) & 127)];
        size_t off = (size_t)(cbase + a) * N_NODES + rbase + tx * 8;
        *(float4*)&C[off]     = v0;
        *(float4*)&C[off + 4] = v1;
    }
}

// ---------------------------------------------------------------------------
extern "C" void kernel_launch(void* const* d_in, const int* in_sizes, int n_in,
                              void* d_out, int out_size)
{
    const float* x    = (const float*)d_in[0];
    const float* w1   = (const float*)d_in[1];
    const float* w2   = (const float*)d_in[2];
    const int*   erow = (const int*)  d_in[3];
    const int*   ecol = (const int*)  d_in[4];
    const float* ew   = (const float*)d_in[5];

    float* out   = (float*)d_out;
    float* recon = out;                                   // [N, N]
    float* z     = out + (size_t)N_NODES * N_NODES;       // [N, Z_DIM]

    float *h0, *h, *p;
    cudaGetSymbolAddress((void**)&h0, g_h0);
    cudaGetSymbolAddress((void**)&h,  g_h);
    cudaGetSymbolAddress((void**)&p,  g_p);

    // 1. CSR row pointers
    rowptr_kernel<<<(N_NODES + 256) / 256, 256>>>(erow);

    // 2. h0 = x @ W1   [8192 x 256], 512 blocks
    dim3 g1(HID_DIM / 64, N_NODES / 64);
    sgemm_nn<64, 64, 16><<<g1, 256>>>(x, w1, h0, N_NODES, IN_DIM, HID_DIM);

    // 3. h = relu(spmm(h0))  — float2 lanes
    spmm_kernel<HID_DIM, true><<<N_NODES / 2, dim3(HID_DIM / 2, 2)>>>(h0, ecol, ew, h);

    // 4. p = h @ W2    [8192 x 64], BM=32 -> 256 blocks (occupancy fix)
    dim3 g2(Z_DIM / 64, N_NODES / 32);
    sgemm_nn<32, 64, 16><<<g2, 128>>>(h, w2, p, N_NODES, HID_DIM, Z_DIM);

    // 5. z = spmm(p) -> written directly into output tail
    spmm_kernel<Z_DIM, false><<<N_NODES / 8, dim3(Z_DIM / 2, 8)>>>(p, ecol, ew, z);

    // 6. recon = z @ z^T, symmetric lower-triangle grid
    const int n_tiles = N_NODES / ZT;                        // 64
    const int n_blocks = n_tiles * (n_tiles + 1) / 2;        // 2080
    const int zzt_smem = 2 * Z_DIM * ZLD * (int)sizeof(float);   // 67584 B
    cudaFuncSetAttribute(zzt_sym_kernel, cudaFuncAttributeMaxDynamicSharedMemorySize, zzt_smem);
    zzt_sym_kernel<<<n_blocks, 256, zzt_smem>>>(z, recon);
}